// round 15
// baseline (speedup 1.0000x reference)
#include <cuda_runtime.h>
#include <cuda_bf16.h>
#include <math.h>
#include <stdint.h>

#define E_NN 50000
#define F_NN 25000
#define M_NN 100000
#define P_NN 75000
#define DD   128
#define HDD  384

// ---------------- scratch (device globals; no allocation allowed) ----------------
__device__ float g_h0[F_NN * DD];
__device__ float g_h1[F_NN * DD];
__device__ float g_ws[F_NN * DD];
__device__ float g_wsE[E_NN * DD];
__device__ float g_q[E_NN * HDD];
__device__ float g_k[F_NN * HDD];
__device__ float g_v[F_NN * HDD];
__device__ float g_ep[M_NN * HDD];
// packed bf16 operands (u32 = 2 adjacent-k bf16; planar row-major [row][64])
__device__ uint32_t g_apkH[64 * M_NN];
__device__ uint32_t g_apkL[64 * M_NN];
__device__ uint32_t g_eapkH[64 * P_NN];
__device__ uint32_t g_eapkL[64 * P_NN];
__device__ uint32_t g_wpkH[448 * 1024];   // weights [l][kpair][N]
__device__ uint32_t g_wpkL[448 * 1024];
// CSR structures
__device__ int g_cnt[2 * F_NN + E_NN];
__device__ int g_cur[2 * F_NN + E_NN];
__device__ int g_off1[F_NN + 1];
__device__ int g_off2[F_NN + 1];
__device__ int g_off3[E_NN + 1];
__device__ int g_edg1[P_NN];
__device__ int g_edg2[M_NN];
__device__ int g_edg3[M_NN];

// ---------------- CSR build kernels ----------------
__global__ void fill_int_kernel(int* __restrict__ p, int n) {
    int t = blockIdx.x * blockDim.x + threadIdx.x;
    if (t < n) p[t] = 0;
}

__global__ void hist_kernel(const int* __restrict__ idx, int col, int n,
                            int* __restrict__ cnt) {
    int t = blockIdx.x * blockDim.x + threadIdx.x;
    if (t < n) atomicAdd(&cnt[idx[(size_t)t * 3 + col]], 1);
}

__global__ void scan3_kernel(const int* __restrict__ cntAll, int* __restrict__ curAll,
                             int* __restrict__ off1, int* __restrict__ off2,
                             int* __restrict__ off3) {
    __shared__ int sh[1024];
    __shared__ int carry;
    const int* cnt;
    int* cur;
    int* off;
    int n;
    if (blockIdx.x == 0) { cnt = cntAll; cur = curAll; off = off1; n = F_NN; }
    else if (blockIdx.x == 1) { cnt = cntAll + F_NN; cur = curAll + F_NN; off = off2; n = F_NN; }
    else { cnt = cntAll + 2 * F_NN; cur = curAll + 2 * F_NN; off = off3; n = E_NN; }
    int tid = threadIdx.x;
    if (tid == 0) carry = 0;
    __syncthreads();
    for (int base = 0; base < n; base += 1024) {
        int i = base + tid;
        int val = (i < n) ? cnt[i] : 0;
        sh[tid] = val;
        __syncthreads();
        for (int o = 1; o < 1024; o <<= 1) {
            int t = (tid >= o) ? sh[tid - o] : 0;
            __syncthreads();
            sh[tid] += t;
            __syncthreads();
        }
        int exc = sh[tid] - val;
        if (i < n) { off[i] = carry + exc; cur[i] = carry + exc; }
        __syncthreads();
        if (tid == 1023) carry += sh[1023];
        __syncthreads();
    }
    if (tid == 0) off[n] = carry;
}

__global__ void csr_scatter_kernel(const int* __restrict__ idx, int col, int n,
                                   int* __restrict__ cur, int* __restrict__ edg) {
    int t = blockIdx.x * blockDim.x + threadIdx.x;
    if (t >= n) return;
    int node = idx[(size_t)t * 3 + col];
    int pos = atomicAdd(&cur[node], 1);
    edg[pos] = t;
}

// ---------------- bf16 hi/lo packing helpers ----------------
__device__ __forceinline__ uint32_t bf2(float e0, float e1) {  // e0 -> low half
    __nv_bfloat162 t = __floats2bfloat162_rn(e0, e1);
    return *(uint32_t*)&t;
}
__device__ __forceinline__ float bfr(float x) {
    return __bfloat162float(__float2bfloat16_rn(x));
}

// activations: A[M][128] float (+optional gather/sign) -> planar bf16 hi/lo [r][64]
__global__ void conv_act_kernel(const float* __restrict__ A, int M,
                                const int* __restrict__ idx, int col, int sgnCol,
                                uint32_t* __restrict__ outH,
                                uint32_t* __restrict__ outL) {
    int t = blockIdx.x * blockDim.x + threadIdx.x;
    int r = t >> 5;
    if (r >= M) return;
    int lane = t & 31;
    int src = r;
    float sgn = 1.0f;
    if (idx) {
        src = idx[(size_t)r * 3 + col];
        if (sgnCol >= 0) sgn = (float)idx[(size_t)r * 3 + sgnCol];
    }
    float4 v = ((const float4*)(A + (size_t)src * 128))[lane];
    v.x *= sgn; v.y *= sgn; v.z *= sgn; v.w *= sgn;
    float h0 = bfr(v.x), h1 = bfr(v.y), h2 = bfr(v.z), h3 = bfr(v.w);
    size_t o = (size_t)r * 64 + lane * 2;
    outH[o + 0] = bf2(h0, h1);
    outH[o + 1] = bf2(h2, h3);
    outL[o + 0] = bf2(v.x - h0, v.y - h1);
    outL[o + 1] = bf2(v.z - h2, v.w - h3);
}

// all weights converted in one kernel: W[L][128][N] -> [L][kpair][N] u32
struct WSpec {
    const float* W[12];
    int start[12];
    int N[12];
    int total;
};
__global__ void conv_w_all_kernel(WSpec ws,
                                  uint32_t* __restrict__ outH,
                                  uint32_t* __restrict__ outL) {
    int t = blockIdx.x * blockDim.x + threadIdx.x;
    if (t >= ws.total) return;
    int f = 0;
#pragma unroll
    for (int i = 1; i < 12; i++)
        if (t >= ws.start[i]) f = i;
    int rel = t - ws.start[f];
    int N = ws.N[f];
    int p2 = rel / N;          // (l*64 + pair)
    int n = rel - p2 * N;
    const float* src = ws.W[f] + (size_t)(2 * p2) * N + n;  // l*128 + 2*pair
    float v0 = src[0];
    float v1 = src[N];
    float h0 = bfr(v0), h1 = bfr(v1);
    outH[t] = bf2(h0, h1);
    outL[t] = bf2(v0 - h0, v1 - h1);
}

// initial aggregation -> packed apk
__global__ void aggr_conv_kernel(const int* __restrict__ off, const int* __restrict__ edg,
                                 const int* __restrict__ cob,
                                 const float* __restrict__ hE,
                                 uint32_t* __restrict__ outH,
                                 uint32_t* __restrict__ outL) {
    int f = blockIdx.x * 8 + (threadIdx.x >> 5);
    if (f >= F_NN) return;
    int lane = threadIdx.x & 31;
    float4 acc = make_float4(0.f, 0.f, 0.f, 0.f);
    int e1 = off[f + 1];
    for (int i = off[f]; i < e1; i++) {
        int eid = edg[i];
        int ecol = cob[(size_t)eid * 3 + 0];
        float sgn = (float)cob[(size_t)eid * 3 + 2];
        float4 x = ((const float4*)(hE + (size_t)ecol * DD))[lane];
        acc.x += sgn * x.x; acc.y += sgn * x.y;
        acc.z += sgn * x.z; acc.w += sgn * x.w;
    }
    float h0 = bfr(acc.x), h1 = bfr(acc.y), h2 = bfr(acc.z), h3 = bfr(acc.w);
    size_t o = (size_t)f * 64 + lane * 2;
    outH[o + 0] = bf2(h0, h1);
    outH[o + 1] = bf2(h2, h3);
    outL[o + 0] = bf2(acc.x - h0, acc.y - h1);
    outL[o + 1] = bf2(acc.z - h2, acc.w - h3);
}

// ---------------- BF16x3 tensor-core GEMM (full-K resident tiles, no pipeline) ----------------
__device__ __forceinline__ void mma_bf16(float* d,
                                         uint32_t a0, uint32_t a1, uint32_t a2, uint32_t a3,
                                         uint32_t b0, uint32_t b1) {
    asm volatile(
        "mma.sync.aligned.m16n8k16.row.col.f32.bf16.bf16.f32 "
        "{%0,%1,%2,%3}, {%4,%5,%6,%7}, {%8,%9}, {%0,%1,%2,%3};\n"
        : "+f"(d[0]), "+f"(d[1]), "+f"(d[2]), "+f"(d[3])
        : "r"(a0), "r"(a1), "r"(a2), "r"(a3), "r"(b0), "r"(b1));
}

__device__ __forceinline__ void cp16(void* smemDst, const void* gsrc) {
    uint32_t s = (uint32_t)__cvta_generic_to_shared(smemDst);
    asm volatile("cp.async.ca.shared.global [%0], [%1], 16;\n" :: "r"(s), "l"(gsrc));
}
#define CP_COMMIT() asm volatile("cp.async.commit_group;\n")
#define CP_WAIT0()  asm volatile("cp.async.wait_group 0;\n")

#define ASTRIDE_F 68                     // u32 per A row (64 used + 4 pad); (4g+q)%32 distinct
#define BSTRIDE_F 136                    // u32 per B kpair row (128 used + 8 pad); (8q+g)%32 distinct
#define A_TILE_U32 (128 * ASTRIDE_F)     // 8704
#define B_TILE_U32 (64 * BSTRIDE_F)      // 8704
#define GEMM_SMEM ((2 * A_TILE_U32 + 2 * B_TILE_U32) * 4)   // 139264 bytes

struct GSegs {
    const uint32_t* BH[4];
    const uint32_t* BL[4];
    const float* bias[4];
    float* C[4];
    uint32_t* eH[4];   // optional packed output (segment N must be 128)
    uint32_t* eL[4];
    int N[4];
    int acc[4];
    int start[4];
    int nseg;
};

__global__ __launch_bounds__(256, 1) void gemm_multi(
    const uint32_t* __restrict__ apkH, const uint32_t* __restrict__ apkL,
    int M, GSegs segs)
{
    extern __shared__ uint32_t smu[];
    uint32_t* AsH = smu;
    uint32_t* AsL = smu + A_TILE_U32;
    uint32_t* BsH = smu + 2 * A_TILE_U32;
    uint32_t* BsL = smu + 2 * A_TILE_U32 + B_TILE_U32;

    const int tid = threadIdx.x;
    const int lane = tid & 31;
    const int warp = tid >> 5;
    const int warp_m = warp & 1;
    const int warp_n = warp >> 1;
    const int row0 = blockIdx.y * 128;

    // segment resolution
    int s = 0;
#pragma unroll
    for (int t = 1; t < 4; t++)
        if (t < segs.nseg && (int)blockIdx.x >= segs.start[t]) s = t;
    const uint32_t* BHp = segs.BH[s];
    const uint32_t* BLp = segs.BL[s];
    const float* bias = segs.bias[s];
    float* C = segs.C[s];
    uint32_t* eH = segs.eH[s];
    uint32_t* eL = segs.eL[s];
    const int N = segs.N[s];
    const int accum = segs.acc[s];
    const int col0 = (blockIdx.x - segs.start[s]) * 128;

    const int grp = lane >> 2;
    const int qid = lane & 3;

    // ---- load full-K tiles once ----
    {
        const int a_r = tid >> 1;
        const int a_cb = (tid & 1) * 4;
        const int arow = (row0 + a_r < M) ? (row0 + a_r) : (M - 1);
        const uint32_t* gAH = apkH + (size_t)arow * 64;
        const uint32_t* gAL = apkL + (size_t)arow * 64;
#pragma unroll
        for (int p = 0; p < 8; p++) {
            int cb = a_cb + p * 8;
            cp16(&AsH[a_r * ASTRIDE_F + cb], gAH + cb);
            cp16(&AsL[a_r * ASTRIDE_F + cb], gAL + cb);
        }
        const int b_kp0 = tid >> 5;
        const int b_ch = (tid & 31) * 4;
#pragma unroll
        for (int p = 0; p < 8; p++) {
            int kp = b_kp0 + p * 8;
            cp16(&BsH[kp * BSTRIDE_F + b_ch], BHp + (size_t)kp * N + col0 + b_ch);
            cp16(&BsL[kp * BSTRIDE_F + b_ch], BLp + (size_t)kp * N + col0 + b_ch);
        }
    }
    CP_COMMIT();
    CP_WAIT0();
    __syncthreads();

    float acc[4][4][4];
#pragma unroll
    for (int i = 0; i < 4; i++)
#pragma unroll
        for (int j = 0; j < 4; j++)
#pragma unroll
            for (int r = 0; r < 4; r++) acc[i][j][r] = 0.f;

    // ---- 8 k-iterations, no barriers ----
#pragma unroll
    for (int it = 0; it < 8; it++) {
        const int kq0 = it * 8 + qid;
        uint32_t afH[4][4], afL[4][4];
        uint32_t bfH[4][2], bfL[4][2];
#pragma unroll
        for (int i = 0; i < 4; i++) {
            int mr = warp_m * 64 + i * 16 + grp;
            afH[i][0] = AsH[mr * ASTRIDE_F + kq0];
            afH[i][1] = AsH[(mr + 8) * ASTRIDE_F + kq0];
            afH[i][2] = AsH[mr * ASTRIDE_F + kq0 + 4];
            afH[i][3] = AsH[(mr + 8) * ASTRIDE_F + kq0 + 4];
            afL[i][0] = AsL[mr * ASTRIDE_F + kq0];
            afL[i][1] = AsL[(mr + 8) * ASTRIDE_F + kq0];
            afL[i][2] = AsL[mr * ASTRIDE_F + kq0 + 4];
            afL[i][3] = AsL[(mr + 8) * ASTRIDE_F + kq0 + 4];
        }
#pragma unroll
        for (int j = 0; j < 4; j++) {
            int nb = warp_n * 32 + j * 8 + grp;
            bfH[j][0] = BsH[kq0 * BSTRIDE_F + nb];
            bfH[j][1] = BsH[(kq0 + 4) * BSTRIDE_F + nb];
            bfL[j][0] = BsL[kq0 * BSTRIDE_F + nb];
            bfL[j][1] = BsL[(kq0 + 4) * BSTRIDE_F + nb];
        }
#pragma unroll
        for (int i = 0; i < 4; i++)
#pragma unroll
            for (int j = 0; j < 4; j++) {
                mma_bf16(acc[i][j], afH[i][0], afH[i][1], afH[i][2], afH[i][3],
                         bfH[j][0], bfH[j][1]);
                mma_bf16(acc[i][j], afH[i][0], afH[i][1], afH[i][2], afH[i][3],
                         bfL[j][0], bfL[j][1]);
                mma_bf16(acc[i][j], afL[i][0], afL[i][1], afL[i][2], afL[i][3],
                         bfH[j][0], bfH[j][1]);
            }
    }

    // ---- epilogue ----
#pragma unroll
    for (int i = 0; i < 4; i++) {
        int row = row0 + warp_m * 64 + i * 16 + grp;
#pragma unroll
        for (int j = 0; j < 4; j++) {
            int col = col0 + warp_n * 32 + j * 8 + qid * 2;
#pragma unroll
            for (int half = 0; half < 2; half++) {
                int r = row + half * 8;
                if (r >= M) continue;
                float2 res;
                res.x = acc[i][j][half * 2 + 0];
                res.y = acc[i][j][half * 2 + 1];
                if (bias) {
                    res.x += bias[col + 0];
                    res.y += bias[col + 1];
                }
                float2* cp = (float2*)(C + (size_t)r * N + col);
                if (accum) {
                    float2 old = *cp;
                    res.x += old.x;
                    res.y += old.y;
                }
                *cp = res;
                if (eH) {
                    float hx = bfr(res.x), hy = bfr(res.y);
                    size_t o = (size_t)r * 64 + (col >> 1);
                    eH[o] = bf2(hx, hy);
                    eL[o] = bf2(res.x - hx, res.y - hy);
                }
            }
        }
    }
}

// ---------------- fused CSR attention (online softmax, warp per dst node) ----------------
__global__ void attn_csr_kernel(
    const int* __restrict__ off, const int* __restrict__ edg,
    const int* __restrict__ idx, int srcCol,
    const float* __restrict__ q, const float* __restrict__ k,
    const float* __restrict__ v, const float* __restrict__ ep,
    const float* __restrict__ hin, const float* __restrict__ ws,
    float* __restrict__ outp,
    uint32_t* __restrict__ apkH, uint32_t* __restrict__ apkL,
    int Nn)
{
    int node = blockIdx.x * 8 + (threadIdx.x >> 5);
    if (node >= Nn) return;
    int lane = threadIdx.x & 31;
    const float4* qp = (const float4*)(q + (size_t)node * HDD);
    float4 qv[3];
    qv[0] = qp[lane]; qv[1] = qp[32 + lane]; qv[2] = qp[64 + lane];
    float m[3] = {-INFINITY, -INFINITY, -INFINITY};
    float dd[3] = {0.f, 0.f, 0.f};
    float4 aa[3];
    aa[0] = aa[1] = aa[2] = make_float4(0.f, 0.f, 0.f, 0.f);

    int iend = off[node + 1];
    for (int i = off[node]; i < iend; i++) {
        int eid = edg[i];
        int src = idx[(size_t)eid * 3 + srcCol];
        const float4* kp = (const float4*)(k + (size_t)src * HDD);
        const float4* vp = (const float4*)(v + (size_t)src * HDD);
        const float4* epp = (const float4*)(ep + (size_t)eid * HDD);
#pragma unroll
        for (int h = 0; h < 3; h++) {
            float4 kv = kp[h * 32 + lane];
            float4 ev = epp[h * 32 + lane];
            float4 vv = vp[h * 32 + lane];
            float sc = qv[h].x * (kv.x + ev.x) + qv[h].y * (kv.y + ev.y) +
                       qv[h].z * (kv.z + ev.z) + qv[h].w * (kv.w + ev.w);
#pragma unroll
            for (int o = 16; o > 0; o >>= 1) sc += __shfl_xor_sync(0xffffffffu, sc, o);
            sc *= 0.08838834764831845f;
            float nm = fmaxf(m[h], sc);
            float sl = __expf(m[h] - nm);
            float p = __expf(sc - nm);
            dd[h] = dd[h] * sl + p;
            aa[h].x = aa[h].x * sl + p * (vv.x + ev.x);
            aa[h].y = aa[h].y * sl + p * (vv.y + ev.y);
            aa[h].z = aa[h].z * sl + p * (vv.z + ev.z);
            aa[h].w = aa[h].w * sl + p * (vv.w + ev.w);
            m[h] = nm;
        }
    }

    float4 o4 = make_float4(0.f, 0.f, 0.f, 0.f);
#pragma unroll
    for (int h = 0; h < 3; h++) {
        float inv = (dd[h] > 0.f) ? 1.f / (dd[h] + 1e-16f) : 0.f;
        o4.x += aa[h].x * inv;
        o4.y += aa[h].y * inv;
        o4.z += aa[h].z * inv;
        o4.w += aa[h].w * inv;
    }
    const float third = 1.0f / 3.0f;
    o4.x *= third; o4.y *= third; o4.z *= third; o4.w *= third;
    if (hin) {
        float4 t = ((const float4*)(hin + (size_t)node * DD))[lane];
        o4.x += t.x; o4.y += t.y; o4.z += t.z; o4.w += t.w;
    }
    if (ws) {
        float4 t = ((const float4*)(ws + (size_t)node * DD))[lane];
        o4.x += t.x; o4.y += t.y; o4.z += t.z; o4.w += t.w;
    }
    ((float4*)(outp + (size_t)node * DD))[lane] = o4;
    if (apkH) {
        float h0 = bfr(o4.x), h1 = bfr(o4.y), h2 = bfr(o4.z), h3 = bfr(o4.w);
        size_t o = (size_t)node * 64 + lane * 2;
        apkH[o + 0] = bf2(h0, h1);
        apkH[o + 1] = bf2(h2, h3);
        apkL[o + 0] = bf2(o4.x - h0, o4.y - h1);
        apkL[o + 1] = bf2(o4.z - h2, o4.w - h3);
    }
}

// ---------------- host orchestration ----------------
static inline int cdiv(int a, int b) { return (a + b - 1) / b; }

extern "C" void kernel_launch(void* const* d_in, const int* in_sizes, int n_in,
                              void* d_out, int out_size) {
    const float* h_dE = (const float*)d_in[0];
    const float* h_dF = (const float*)d_in[1];
    const int* cob = (const int*)d_in[2];
    const int* nn = (const int*)d_in[3];
    const float* aggr_W = (const float*)d_in[4];
    const float* aggr_b = (const float*)d_in[5];
    const float* ctr_W = (const float*)d_in[6];
    const float* ctr_b = (const float*)d_in[7];
    const float* f_Wq = (const float*)d_in[8];
    const float* f_bq = (const float*)d_in[9];
    const float* f_Wk = (const float*)d_in[10];
    const float* f_bk = (const float*)d_in[11];
    const float* f_Wv = (const float*)d_in[12];
    const float* f_bv = (const float*)d_in[13];
    const float* f_We = (const float*)d_in[14];
    const float* f_Ws = (const float*)d_in[15];
    const float* f_bs = (const float*)d_in[16];
    const float* e_Wq = (const float*)d_in[17];
    const float* e_bq = (const float*)d_in[18];
    const float* e_Wk = (const float*)d_in[19];
    const float* e_bk = (const float*)d_in[20];
    const float* e_Wv = (const float*)d_in[21];
    const float* e_bv = (const float*)d_in[22];
    const float* e_We = (const float*)d_in[23];
    const float* e_Ws = (const float*)d_in[24];
    const float* e_bs = (const float*)d_in[25];
    float* out = (float*)d_out;

    cudaFuncSetAttribute(gemm_multi, cudaFuncAttributeMaxDynamicSharedMemorySize, GEMM_SMEM);

    float *h0, *h1, *wsF, *wsE, *q, *k, *v, *ep;
    uint32_t *apkH, *apkL, *eapkH, *eapkL, *wpkH, *wpkL;
    int *cnt, *cur, *off1, *off2, *off3, *edg1, *edg2, *edg3;
    cudaGetSymbolAddress((void**)&h0, g_h0);
    cudaGetSymbolAddress((void**)&h1, g_h1);
    cudaGetSymbolAddress((void**)&wsF, g_ws);
    cudaGetSymbolAddress((void**)&wsE, g_wsE);
    cudaGetSymbolAddress((void**)&q, g_q);
    cudaGetSymbolAddress((void**)&k, g_k);
    cudaGetSymbolAddress((void**)&v, g_v);
    cudaGetSymbolAddress((void**)&ep, g_ep);
    cudaGetSymbolAddress((void**)&apkH, g_apkH);
    cudaGetSymbolAddress((void**)&apkL, g_apkL);
    cudaGetSymbolAddress((void**)&eapkH, g_eapkH);
    cudaGetSymbolAddress((void**)&eapkL, g_eapkL);
    cudaGetSymbolAddress((void**)&wpkH, g_wpkH);
    cudaGetSymbolAddress((void**)&wpkL, g_wpkL);
    cudaGetSymbolAddress((void**)&cnt, g_cnt);
    cudaGetSymbolAddress((void**)&cur, g_cur);
    cudaGetSymbolAddress((void**)&off1, g_off1);
    cudaGetSymbolAddress((void**)&off2, g_off2);
    cudaGetSymbolAddress((void**)&off3, g_off3);
    cudaGetSymbolAddress((void**)&edg1, g_edg1);
    cudaGetSymbolAddress((void**)&edg2, g_edg2);
    cudaGetSymbolAddress((void**)&edg3, g_edg3);

    const int FY = cdiv(F_NN, 128);
    const int EY = cdiv(E_NN, 128);
    const int PY = cdiv(P_NN, 128);
    const int MY = cdiv(M_NN, 128);

    // ---- CSR build ----
    const int NCNT = 2 * F_NN + E_NN;
    fill_int_kernel<<<cdiv(NCNT, 256), 256>>>(cnt, NCNT);
    hist_kernel<<<cdiv(P_NN, 256), 256>>>(nn, 1, P_NN, cnt);
    hist_kernel<<<cdiv(M_NN, 256), 256>>>(cob, 1, M_NN, cnt + F_NN);
    hist_kernel<<<cdiv(M_NN, 256), 256>>>(cob, 0, M_NN, cnt + 2 * F_NN);
    scan3_kernel<<<3, 1024>>>(cnt, cur, off1, off2, off3);
    csr_scatter_kernel<<<cdiv(P_NN, 256), 256>>>(nn, 1, P_NN, cur, edg1);
    csr_scatter_kernel<<<cdiv(M_NN, 256), 256>>>(cob, 1, M_NN, cur + F_NN, edg2);
    csr_scatter_kernel<<<cdiv(M_NN, 256), 256>>>(cob, 0, M_NN, cur + 2 * F_NN, edg3);

    // ---- weight conversion (single kernel, [l][kpair][N]) ----
    WSpec wsp;
    {
        const float* Ws[12] = {aggr_W, ctr_W, f_Wq, f_Wk, f_Wv, f_We, f_Ws,
                               e_Wq, e_Wk, e_Wv, e_We, e_Ws};
        int Ns[12] = {128, 128, 384, 384, 384, 384, 128, 384, 384, 384, 384, 128};
        int Ls[12] = {1, 1, 3, 3, 3, 3, 3, 1, 1, 1, 1, 1};
        int o = 0;
        for (int i = 0; i < 12; i++) {
            wsp.W[i] = Ws[i];
            wsp.start[i] = o;
            wsp.N[i] = Ns[i];
            o += 64 * Ns[i] * Ls[i];
        }
        wsp.total = o;
    }
    conv_w_all_kernel<<<cdiv(wsp.total, 256), 256>>>(wsp, wpkH, wpkL);
    const int o_aggr = wsp.start[0], o_ctr = wsp.start[1];
    const int o_fq = wsp.start[2], o_fk = wsp.start[3], o_fv = wsp.start[4];
    const int o_fwe = wsp.start[5], o_fws = wsp.start[6];
    const int o_eq = wsp.start[7], o_ek = wsp.start[8], o_ev = wsp.start[9];
    const int o_ewe = wsp.start[10], o_ews = wsp.start[11];

    // ---- init: h0 = aggr@aggr_W + aggr_b + h_dF@ctr_W + ctr_b ----
    aggr_conv_kernel<<<cdiv(F_NN, 8), 256>>>(off2, edg2, cob, h_dE, apkH, apkL);
    {
        GSegs s1 = {};
        s1.BH[0] = wpkH + o_aggr; s1.BL[0] = wpkL + o_aggr; s1.bias[0] = aggr_b;
        s1.C[0] = h0; s1.N[0] = 128; s1.acc[0] = 0; s1.start[0] = 0; s1.nseg = 1;
        gemm_multi<<<dim3(1, FY), 256, GEMM_SMEM>>>(apkH, apkL, F_NN, s1);
    }
    conv_act_kernel<<<cdiv(F_NN * 32, 256), 256>>>(h_dF, F_NN, nullptr, 0, -1, apkH, apkL);
    {
        GSegs s2 = {};
        s2.BH[0] = wpkH + o_ctr; s2.BL[0] = wpkL + o_ctr; s2.bias[0] = ctr_b;
        s2.C[0] = h0; s2.N[0] = 128; s2.acc[0] = 1; s2.start[0] = 0;
        s2.eH[0] = apkH; s2.eL[0] = apkL;   // emit packed h0 for layer-1 GEMM
        s2.nseg = 1;
        gemm_multi<<<dim3(1, FY), 256, GEMM_SMEM>>>(apkH, apkL, F_NN, s2);
    }

    // ea = h_dE[nn[:,2]] packed once (layer-invariant)
    conv_act_kernel<<<cdiv(P_NN * 32, 256), 256>>>(h_dE, P_NN, nn, 2, -1, eapkH, eapkL);

    float* hcur = h0;
    float* hnext = h1;
    for (int l = 0; l < 3; l++) {
        const float* bq = f_bq + (size_t)l * 384;
        const float* bk = f_bk + (size_t)l * 384;
        const float* bv = f_bv + (size_t)l * 384;
        const float* bs = f_bs + (size_t)l * 128;
        const int lo384 = l * 64 * 384;
        const int lo128 = l * 64 * 128;

        GSegs sq = {};
        sq.BH[0] = wpkH + o_fq + lo384;  sq.BL[0] = wpkL + o_fq + lo384;
        sq.bias[0] = bq; sq.C[0] = q;   sq.N[0] = 384; sq.acc[0] = 0; sq.start[0] = 0;
        sq.BH[1] = wpkH + o_fk + lo384;  sq.BL[1] = wpkL + o_fk + lo384;
        sq.bias[1] = bk; sq.C[1] = k;   sq.N[1] = 384; sq.acc[1] = 0; sq.start[1] = 3;
        sq.BH[2] = wpkH + o_fv + lo384;  sq.BL[2] = wpkL + o_fv + lo384;
        sq.bias[2] = bv; sq.C[2] = v;   sq.N[2] = 384; sq.acc[2] = 0; sq.start[2] = 6;
        sq.BH[3] = wpkH + o_fws + lo128; sq.BL[3] = wpkL + o_fws + lo128;
        sq.bias[3] = bs; sq.C[3] = wsF; sq.N[3] = 128; sq.acc[3] = 0; sq.start[3] = 9;
        sq.nseg = 4;
        gemm_multi<<<dim3(10, FY), 256, GEMM_SMEM>>>(apkH, apkL, F_NN, sq);

        GSegs se = {};
        se.BH[0] = wpkH + o_fwe + lo384; se.BL[0] = wpkL + o_fwe + lo384;
        se.bias[0] = nullptr; se.C[0] = ep; se.N[0] = 384; se.acc[0] = 0; se.start[0] = 0;
        se.nseg = 1;
        gemm_multi<<<dim3(3, PY), 256, GEMM_SMEM>>>(eapkH, eapkL, P_NN, se);

        // fused attention + residual + Ws + next-layer packing
        attn_csr_kernel<<<cdiv(F_NN, 8), 256>>>(off1, edg1, nn, 0,
                                                q, k, v, ep, hcur, wsF,
                                                hnext, apkH, apkL, F_NN);

        float* tmp = hcur; hcur = hnext; hnext = tmp;
    }

    // ---- final cross attention: F -> E over cobdry edges ----
    {
        conv_act_kernel<<<cdiv(E_NN * 32, 256), 256>>>(h_dE, E_NN, nullptr, 0, -1, eapkH, eapkL);
        GSegs sq = {};
        sq.BH[0] = wpkH + o_eq;  sq.BL[0] = wpkL + o_eq;
        sq.bias[0] = e_bq; sq.C[0] = q;   sq.N[0] = 384; sq.acc[0] = 0; sq.start[0] = 0;
        sq.BH[1] = wpkH + o_ews; sq.BL[1] = wpkL + o_ews;
        sq.bias[1] = e_bs; sq.C[1] = wsE; sq.N[1] = 128; sq.acc[1] = 0; sq.start[1] = 3;
        sq.nseg = 2;
        gemm_multi<<<dim3(4, EY), 256, GEMM_SMEM>>>(eapkH, eapkL, E_NN, sq);

        GSegs skv = {};
        skv.BH[0] = wpkH + o_ek; skv.BL[0] = wpkL + o_ek;
        skv.bias[0] = e_bk; skv.C[0] = k; skv.N[0] = 384; skv.acc[0] = 0; skv.start[0] = 0;
        skv.BH[1] = wpkH + o_ev; skv.BL[1] = wpkL + o_ev;
        skv.bias[1] = e_bv; skv.C[1] = v; skv.N[1] = 384; skv.acc[1] = 0; skv.start[1] = 3;
        skv.nseg = 2;
        gemm_multi<<<dim3(6, FY), 256, GEMM_SMEM>>>(apkH, apkL, F_NN, skv);

        conv_act_kernel<<<cdiv(M_NN * 32, 256), 256>>>(hcur, M_NN, cob, 1, 2, apkH, apkL);
        GSegs se = {};
        se.BH[0] = wpkH + o_ewe; se.BL[0] = wpkL + o_ewe;
        se.bias[0] = nullptr; se.C[0] = ep; se.N[0] = 384; se.acc[0] = 0; se.start[0] = 0;
        se.nseg = 1;
        gemm_multi<<<dim3(3, MY), 256, GEMM_SMEM>>>(apkH, apkL, M_NN, se);

        attn_csr_kernel<<<cdiv(E_NN, 8), 256>>>(off3, edg3, cob, 1,
                                                q, k, v, ep, nullptr, wsE,
                                                out, nullptr, nullptr, E_NN);
    }
}

// round 17
// speedup vs baseline: 1.2912x; 1.2912x over previous
#include <cuda_runtime.h>
#include <cuda_bf16.h>
#include <math.h>
#include <stdint.h>

#define E_NN 50000
#define F_NN 25000
#define M_NN 100000
#define P_NN 75000
#define DD   128
#define HDD  384

// ---------------- scratch (device globals; no allocation allowed) ----------------
__device__ float g_h0[F_NN * DD];
__device__ float g_h1[F_NN * DD];
__device__ float g_ws[F_NN * DD];
__device__ float g_wsE[E_NN * DD];
__device__ float g_q[E_NN * HDD];
__device__ float g_k[F_NN * HDD];
__device__ float g_v[F_NN * HDD];
__device__ float g_ep[E_NN * HDD];     // epE (E rows) for layers; hWe (F rows) for final
// packed bf16 operands (u32 = 2 adjacent-k bf16; planar row-major [row][64])
__device__ uint32_t g_apkH[64 * F_NN];     // F-row activations
__device__ uint32_t g_apkL[64 * F_NN];
__device__ uint32_t g_edpkH[64 * E_NN];    // packed h_dE (E rows, packed once)
__device__ uint32_t g_edpkL[64 * E_NN];
__device__ uint32_t g_wpkH[448 * 1024];    // weights [l][kpair][N]
__device__ uint32_t g_wpkL[448 * 1024];
// CSR structures: [0]=nn by dst(col1), [1]=cob by f(col1), [2]=cob by e(col0)
__device__ int g_cnt[2 * F_NN + E_NN];
__device__ int g_cur[2 * F_NN + E_NN];
__device__ int g_off1[F_NN + 1];
__device__ int g_off2[F_NN + 1];
__device__ int g_off3[E_NN + 1];
__device__ int g_edg1[P_NN];
__device__ int g_edg2[M_NN];
__device__ int g_edg3[M_NN];

// ---------------- CSR build kernels ----------------
__global__ void fill_int_kernel(int* __restrict__ p, int n) {
    int t = blockIdx.x * blockDim.x + threadIdx.x;
    if (t < n) p[t] = 0;
}

__global__ void hist_kernel(const int* __restrict__ idx, int col, int n,
                            int* __restrict__ cnt) {
    int t = blockIdx.x * blockDim.x + threadIdx.x;
    if (t < n) atomicAdd(&cnt[idx[(size_t)t * 3 + col]], 1);
}

__global__ void scan3_kernel(const int* __restrict__ cntAll, int* __restrict__ curAll,
                             int* __restrict__ off1, int* __restrict__ off2,
                             int* __restrict__ off3) {
    __shared__ int sh[1024];
    __shared__ int carry;
    const int* cnt;
    int* cur;
    int* off;
    int n;
    if (blockIdx.x == 0) { cnt = cntAll; cur = curAll; off = off1; n = F_NN; }
    else if (blockIdx.x == 1) { cnt = cntAll + F_NN; cur = curAll + F_NN; off = off2; n = F_NN; }
    else { cnt = cntAll + 2 * F_NN; cur = curAll + 2 * F_NN; off = off3; n = E_NN; }
    int tid = threadIdx.x;
    if (tid == 0) carry = 0;
    __syncthreads();
    for (int base = 0; base < n; base += 1024) {
        int i = base + tid;
        int val = (i < n) ? cnt[i] : 0;
        sh[tid] = val;
        __syncthreads();
        for (int o = 1; o < 1024; o <<= 1) {
            int t = (tid >= o) ? sh[tid - o] : 0;
            __syncthreads();
            sh[tid] += t;
            __syncthreads();
        }
        int exc = sh[tid] - val;
        if (i < n) { off[i] = carry + exc; cur[i] = carry + exc; }
        __syncthreads();
        if (tid == 1023) carry += sh[1023];
        __syncthreads();
    }
    if (tid == 0) off[n] = carry;
}

__global__ void csr_scatter_kernel(const int* __restrict__ idx, int col, int n,
                                   int* __restrict__ cur, int* __restrict__ edg) {
    int t = blockIdx.x * blockDim.x + threadIdx.x;
    if (t >= n) return;
    int node = idx[(size_t)t * 3 + col];
    int pos = atomicAdd(&cur[node], 1);
    edg[pos] = t;
}

// ---------------- bf16 hi/lo packing helpers ----------------
__device__ __forceinline__ uint32_t bf2(float e0, float e1) {  // e0 -> low half
    __nv_bfloat162 t = __floats2bfloat162_rn(e0, e1);
    return *(uint32_t*)&t;
}
__device__ __forceinline__ float bfr(float x) {
    return __bfloat162float(__float2bfloat16_rn(x));
}

// activations: A[M][128] float -> planar bf16 hi/lo [r][64]
__global__ void conv_act_kernel(const float* __restrict__ A, int M,
                                uint32_t* __restrict__ outH,
                                uint32_t* __restrict__ outL) {
    int t = blockIdx.x * blockDim.x + threadIdx.x;
    int r = t >> 5;
    if (r >= M) return;
    int lane = t & 31;
    float4 v = ((const float4*)(A + (size_t)r * 128))[lane];
    float h0 = bfr(v.x), h1 = bfr(v.y), h2 = bfr(v.z), h3 = bfr(v.w);
    size_t o = (size_t)r * 64 + lane * 2;
    outH[o + 0] = bf2(h0, h1);
    outH[o + 1] = bf2(h2, h3);
    outL[o + 0] = bf2(v.x - h0, v.y - h1);
    outL[o + 1] = bf2(v.z - h2, v.w - h3);
}

// all weights converted in one kernel: W[L][128][N] -> [L][kpair][N] u32
struct WSpec {
    const float* W[12];
    int start[12];
    int N[12];
    int total;
};
__global__ void conv_w_all_kernel(WSpec ws,
                                  uint32_t* __restrict__ outH,
                                  uint32_t* __restrict__ outL) {
    int t = blockIdx.x * blockDim.x + threadIdx.x;
    if (t >= ws.total) return;
    int f = 0;
#pragma unroll
    for (int i = 1; i < 12; i++)
        if (t >= ws.start[i]) f = i;
    int rel = t - ws.start[f];
    int N = ws.N[f];
    int p2 = rel / N;          // (l*64 + pair)
    int n = rel - p2 * N;
    const float* src = ws.W[f] + (size_t)(2 * p2) * N + n;  // row l*128 + 2*pair
    float v0 = src[0];
    float v1 = src[N];
    float h0 = bfr(v0), h1 = bfr(v1);
    outH[t] = bf2(h0, h1);
    outL[t] = bf2(v0 - h0, v1 - h1);
}

// initial aggregation -> packed apk (F rows)
__global__ void aggr_conv_kernel(const int* __restrict__ off, const int* __restrict__ edg,
                                 const int* __restrict__ cob,
                                 const float* __restrict__ hE,
                                 uint32_t* __restrict__ outH,
                                 uint32_t* __restrict__ outL) {
    int f = blockIdx.x * 8 + (threadIdx.x >> 5);
    if (f >= F_NN) return;
    int lane = threadIdx.x & 31;
    float4 acc = make_float4(0.f, 0.f, 0.f, 0.f);
    int e1 = off[f + 1];
    for (int i = off[f]; i < e1; i++) {
        int eid = edg[i];
        int ecol = cob[(size_t)eid * 3 + 0];
        float sgn = (float)cob[(size_t)eid * 3 + 2];
        float4 x = ((const float4*)(hE + (size_t)ecol * DD))[lane];
        acc.x += sgn * x.x; acc.y += sgn * x.y;
        acc.z += sgn * x.z; acc.w += sgn * x.w;
    }
    float h0 = bfr(acc.x), h1 = bfr(acc.y), h2 = bfr(acc.z), h3 = bfr(acc.w);
    size_t o = (size_t)f * 64 + lane * 2;
    outH[o + 0] = bf2(h0, h1);
    outH[o + 1] = bf2(h2, h3);
    outL[o + 0] = bf2(acc.x - h0, acc.y - h1);
    outL[o + 1] = bf2(acc.z - h2, acc.w - h3);
}

// ---------------- BF16x3 tensor-core GEMM (R8-proven: 3-stage pipeline) ----------------
__device__ __forceinline__ void mma_bf16(float* d,
                                         uint32_t a0, uint32_t a1, uint32_t a2, uint32_t a3,
                                         uint32_t b0, uint32_t b1) {
    asm volatile(
        "mma.sync.aligned.m16n8k16.row.col.f32.bf16.bf16.f32 "
        "{%0,%1,%2,%3}, {%4,%5,%6,%7}, {%8,%9}, {%0,%1,%2,%3};\n"
        : "+f"(d[0]), "+f"(d[1]), "+f"(d[2]), "+f"(d[3])
        : "r"(a0), "r"(a1), "r"(a2), "r"(a3), "r"(b0), "r"(b1));
}

__device__ __forceinline__ void cp16(void* smemDst, const void* gsrc) {
    uint32_t s = (uint32_t)__cvta_generic_to_shared(smemDst);
    asm volatile("cp.async.ca.shared.global [%0], [%1], 16;\n" :: "r"(s), "l"(gsrc));
}
#define CP_COMMIT() asm volatile("cp.async.commit_group;\n")
#define CP_WAIT(n)  asm volatile("cp.async.wait_group %0;\n" :: "n"(n))

#define STAGES 3
#define ASTRIDE 12
#define BSTRIDE 136
#define A_ST_U32 (128 * ASTRIDE)
#define B_ST_U32 (8 * BSTRIDE)
#define GEMM_SMEM (STAGES * (2 * A_ST_U32 + 2 * B_ST_U32) * 4)  // 62976

struct GSegs {
    const uint32_t* BH[4];
    const uint32_t* BL[4];
    const float* bias[4];
    float* C[4];
    uint32_t* eH[4];   // optional packed output (N must be 128)
    uint32_t* eL[4];
    int N[4];
    int acc[4];
    int start[4];
    int nseg;
};

__global__ __launch_bounds__(256, 2) void gemm_multi(
    const uint32_t* __restrict__ apkH, const uint32_t* __restrict__ apkL,
    int M, GSegs segs)
{
    extern __shared__ uint32_t smu[];
    uint32_t* AsH = smu;
    uint32_t* AsL = smu + STAGES * A_ST_U32;
    uint32_t* BsH = smu + 2 * STAGES * A_ST_U32;
    uint32_t* BsL = BsH + STAGES * B_ST_U32;

    const int tid = threadIdx.x;
    const int lane = tid & 31;
    const int warp = tid >> 5;
    const int warp_m = warp & 1;
    const int warp_n = warp >> 1;
    const int row0 = blockIdx.y * 128;

    int s = 0;
#pragma unroll
    for (int t = 1; t < 4; t++)
        if (t < segs.nseg && (int)blockIdx.x >= segs.start[t]) s = t;
    const uint32_t* BHp = segs.BH[s];
    const uint32_t* BLp = segs.BL[s];
    const float* bias = segs.bias[s];
    float* C = segs.C[s];
    uint32_t* eH = segs.eH[s];
    uint32_t* eL = segs.eL[s];
    const int N = segs.N[s];
    const int accum = segs.acc[s];
    const int col0 = (blockIdx.x - segs.start[s]) * 128;

    const int grp = lane >> 2;
    const int qid = lane & 3;

    const int a_m = tid >> 1;
    const int a_c = tid & 1;
    const int b_kp = tid >> 5;
    const int b_ch = tid & 31;

    const int arow = (row0 + a_m < M) ? (row0 + a_m) : (M - 1);
    const uint32_t* gAH = apkH + (size_t)arow * 64 + a_c * 4;
    const uint32_t* gAL = apkL + (size_t)arow * 64 + a_c * 4;
    const uint32_t* gBH = BHp + (size_t)b_kp * N + col0 + b_ch * 4;
    const uint32_t* gBL = BLp + (size_t)b_kp * N + col0 + b_ch * 4;

    float acc[4][4][4];
#pragma unroll
    for (int i = 0; i < 4; i++)
#pragma unroll
        for (int j = 0; j < 4; j++)
#pragma unroll
            for (int r = 0; r < 4; r++) acc[i][j][r] = 0.f;

    auto stage = [&](int slot, int kp0) {
        uint32_t* aH = AsH + slot * A_ST_U32 + a_m * ASTRIDE + a_c * 4;
        uint32_t* aL = AsL + slot * A_ST_U32 + a_m * ASTRIDE + a_c * 4;
        cp16(aH, gAH + kp0);
        cp16(aL, gAL + kp0);
        uint32_t* bH = BsH + slot * B_ST_U32 + b_kp * BSTRIDE + b_ch * 4;
        uint32_t* bL = BsL + slot * B_ST_U32 + b_kp * BSTRIDE + b_ch * 4;
        cp16(bH, gBH + (size_t)kp0 * N);
        cp16(bL, gBL + (size_t)kp0 * N);
    };

    stage(0, 0);
    CP_COMMIT();
    stage(1, 8);
    CP_COMMIT();

    for (int it = 0; it < 8; it++) {
        CP_WAIT(1);
        __syncthreads();
        const int buf = it % STAGES;
        const uint32_t* cAH = AsH + buf * A_ST_U32;
        const uint32_t* cAL = AsL + buf * A_ST_U32;
        const uint32_t* cBH = BsH + buf * B_ST_U32;
        const uint32_t* cBL = BsL + buf * B_ST_U32;

        uint32_t afH[4][4], afL[4][4];
        uint32_t bfH[4][2], bfL[4][2];
#pragma unroll
        for (int i = 0; i < 4; i++) {
            int mr = warp_m * 64 + i * 16 + grp;
            afH[i][0] = cAH[mr * ASTRIDE + qid];
            afH[i][1] = cAH[(mr + 8) * ASTRIDE + qid];
            afH[i][2] = cAH[mr * ASTRIDE + qid + 4];
            afH[i][3] = cAH[(mr + 8) * ASTRIDE + qid + 4];
            afL[i][0] = cAL[mr * ASTRIDE + qid];
            afL[i][1] = cAL[(mr + 8) * ASTRIDE + qid];
            afL[i][2] = cAL[mr * ASTRIDE + qid + 4];
            afL[i][3] = cAL[(mr + 8) * ASTRIDE + qid + 4];
        }
#pragma unroll
        for (int j = 0; j < 4; j++) {
            int nb = warp_n * 32 + j * 8 + grp;
            bfH[j][0] = cBH[qid * BSTRIDE + nb];
            bfH[j][1] = cBH[(qid + 4) * BSTRIDE + nb];
            bfL[j][0] = cBL[qid * BSTRIDE + nb];
            bfL[j][1] = cBL[(qid + 4) * BSTRIDE + nb];
        }
#pragma unroll
        for (int i = 0; i < 4; i++)
#pragma unroll
            for (int j = 0; j < 4; j++) {
                mma_bf16(acc[i][j], afH[i][0], afH[i][1], afH[i][2], afH[i][3],
                         bfH[j][0], bfH[j][1]);
                mma_bf16(acc[i][j], afH[i][0], afH[i][1], afH[i][2], afH[i][3],
                         bfL[j][0], bfL[j][1]);
                mma_bf16(acc[i][j], afL[i][0], afL[i][1], afL[i][2], afL[i][3],
                         bfH[j][0], bfH[j][1]);
            }

        int nxt = it + STAGES - 1;
        if (nxt < 8) stage(nxt % STAGES, nxt * 8);
        CP_COMMIT();
    }

#pragma unroll
    for (int i = 0; i < 4; i++) {
        int row = row0 + warp_m * 64 + i * 16 + grp;
#pragma unroll
        for (int j = 0; j < 4; j++) {
            int col = col0 + warp_n * 32 + j * 8 + qid * 2;
#pragma unroll
            for (int half = 0; half < 2; half++) {
                int r = row + half * 8;
                if (r >= M) continue;
                float2 res;
                res.x = acc[i][j][half * 2 + 0];
                res.y = acc[i][j][half * 2 + 1];
                if (bias) {
                    res.x += bias[col + 0];
                    res.y += bias[col + 1];
                }
                float2* cp = (float2*)(C + (size_t)r * N + col);
                if (accum) {
                    float2 old = *cp;
                    res.x += old.x;
                    res.y += old.y;
                }
                *cp = res;
                if (eH) {
                    float hx = bfr(res.x), hy = bfr(res.y);
                    size_t o = (size_t)r * 64 + (col >> 1);
                    eH[o] = bf2(hx, hy);
                    eL[o] = bf2(res.x - hx, res.y - hy);
                }
            }
        }
    }
}

// ---------------- fused CSR attention (online softmax, warp per dst node) ----------------
// ep is indexed per NODE: ep row = idx[eid*3 + epCol]; optional sign from epSgnCol.
__global__ void attn_csr_kernel(
    const int* __restrict__ off, const int* __restrict__ edg,
    const int* __restrict__ idx, int srcCol, int epCol, int epSgnCol,
    const float* __restrict__ q, const float* __restrict__ k,
    const float* __restrict__ v, const float* __restrict__ ep,
    const float* __restrict__ hin, const float* __restrict__ ws,
    float* __restrict__ outp,
    uint32_t* __restrict__ apkH, uint32_t* __restrict__ apkL,
    int Nn)
{
    int node = blockIdx.x * 8 + (threadIdx.x >> 5);
    if (node >= Nn) return;
    int lane = threadIdx.x & 31;
    const float4* qp = (const float4*)(q + (size_t)node * HDD);
    float4 qv[3];
    qv[0] = qp[lane]; qv[1] = qp[32 + lane]; qv[2] = qp[64 + lane];
    float m[3] = {-INFINITY, -INFINITY, -INFINITY};
    float dd[3] = {0.f, 0.f, 0.f};
    float4 aa[3];
    aa[0] = aa[1] = aa[2] = make_float4(0.f, 0.f, 0.f, 0.f);

    int iend = off[node + 1];
    for (int i = off[node]; i < iend; i++) {
        int eid = edg[i];
        int src = idx[(size_t)eid * 3 + srcCol];
        int eprow = idx[(size_t)eid * 3 + epCol];
        float es = (epSgnCol >= 0) ? (float)idx[(size_t)eid * 3 + epSgnCol] : 1.0f;
        const float4* kp = (const float4*)(k + (size_t)src * HDD);
        const float4* vp = (const float4*)(v + (size_t)src * HDD);
        const float4* epp = (const float4*)(ep + (size_t)eprow * HDD);
#pragma unroll
        for (int h = 0; h < 3; h++) {
            float4 kv = kp[h * 32 + lane];
            float4 ev = epp[h * 32 + lane];
            ev.x *= es; ev.y *= es; ev.z *= es; ev.w *= es;
            float4 vv = vp[h * 32 + lane];
            float sc = qv[h].x * (kv.x + ev.x) + qv[h].y * (kv.y + ev.y) +
                       qv[h].z * (kv.z + ev.z) + qv[h].w * (kv.w + ev.w);
#pragma unroll
            for (int o = 16; o > 0; o >>= 1) sc += __shfl_xor_sync(0xffffffffu, sc, o);
            sc *= 0.08838834764831845f;
            float nm = fmaxf(m[h], sc);
            float sl = __expf(m[h] - nm);
            float p = __expf(sc - nm);
            dd[h] = dd[h] * sl + p;
            aa[h].x = aa[h].x * sl + p * (vv.x + ev.x);
            aa[h].y = aa[h].y * sl + p * (vv.y + ev.y);
            aa[h].z = aa[h].z * sl + p * (vv.z + ev.z);
            aa[h].w = aa[h].w * sl + p * (vv.w + ev.w);
            m[h] = nm;
        }
    }

    float4 o4 = make_float4(0.f, 0.f, 0.f, 0.f);
#pragma unroll
    for (int h = 0; h < 3; h++) {
        float inv = (dd[h] > 0.f) ? 1.f / (dd[h] + 1e-16f) : 0.f;
        o4.x += aa[h].x * inv;
        o4.y += aa[h].y * inv;
        o4.z += aa[h].z * inv;
        o4.w += aa[h].w * inv;
    }
    const float third = 1.0f / 3.0f;
    o4.x *= third; o4.y *= third; o4.z *= third; o4.w *= third;
    if (hin) {
        float4 t = ((const float4*)(hin + (size_t)node * DD))[lane];
        o4.x += t.x; o4.y += t.y; o4.z += t.z; o4.w += t.w;
    }
    if (ws) {
        float4 t = ((const float4*)(ws + (size_t)node * DD))[lane];
        o4.x += t.x; o4.y += t.y; o4.z += t.z; o4.w += t.w;
    }
    ((float4*)(outp + (size_t)node * DD))[lane] = o4;
    if (apkH) {
        float h0 = bfr(o4.x), h1 = bfr(o4.y), h2 = bfr(o4.z), h3 = bfr(o4.w);
        size_t o = (size_t)node * 64 + lane * 2;
        apkH[o + 0] = bf2(h0, h1);
        apkH[o + 1] = bf2(h2, h3);
        apkL[o + 0] = bf2(o4.x - h0, o4.y - h1);
        apkL[o + 1] = bf2(o4.z - h2, o4.w - h3);
    }
}

// ---------------- host orchestration ----------------
static inline int cdiv(int a, int b) { return (a + b - 1) / b; }

extern "C" void kernel_launch(void* const* d_in, const int* in_sizes, int n_in,
                              void* d_out, int out_size) {
    const float* h_dE = (const float*)d_in[0];
    const float* h_dF = (const float*)d_in[1];
    const int* cob = (const int*)d_in[2];
    const int* nn = (const int*)d_in[3];
    const float* aggr_W = (const float*)d_in[4];
    const float* aggr_b = (const float*)d_in[5];
    const float* ctr_W = (const float*)d_in[6];
    const float* ctr_b = (const float*)d_in[7];
    const float* f_Wq = (const float*)d_in[8];
    const float* f_bq = (const float*)d_in[9];
    const float* f_Wk = (const float*)d_in[10];
    const float* f_bk = (const float*)d_in[11];
    const float* f_Wv = (const float*)d_in[12];
    const float* f_bv = (const float*)d_in[13];
    const float* f_We = (const float*)d_in[14];
    const float* f_Ws = (const float*)d_in[15];
    const float* f_bs = (const float*)d_in[16];
    const float* e_Wq = (const float*)d_in[17];
    const float* e_bq = (const float*)d_in[18];
    const float* e_Wk = (const float*)d_in[19];
    const float* e_bk = (const float*)d_in[20];
    const float* e_Wv = (const float*)d_in[21];
    const float* e_bv = (const float*)d_in[22];
    const float* e_We = (const float*)d_in[23];
    const float* e_Ws = (const float*)d_in[24];
    const float* e_bs = (const float*)d_in[25];
    float* out = (float*)d_out;

    cudaFuncSetAttribute(gemm_multi, cudaFuncAttributeMaxDynamicSharedMemorySize, GEMM_SMEM);

    float *h0, *h1, *wsF, *wsE, *q, *k, *v, *ep;
    uint32_t *apkH, *apkL, *edpkH, *edpkL, *wpkH, *wpkL;
    int *cnt, *cur, *off1, *off2, *off3, *edg1, *edg2, *edg3;
    cudaGetSymbolAddress((void**)&h0, g_h0);
    cudaGetSymbolAddress((void**)&h1, g_h1);
    cudaGetSymbolAddress((void**)&wsF, g_ws);
    cudaGetSymbolAddress((void**)&wsE, g_wsE);
    cudaGetSymbolAddress((void**)&q, g_q);
    cudaGetSymbolAddress((void**)&k, g_k);
    cudaGetSymbolAddress((void**)&v, g_v);
    cudaGetSymbolAddress((void**)&ep, g_ep);
    cudaGetSymbolAddress((void**)&apkH, g_apkH);
    cudaGetSymbolAddress((void**)&apkL, g_apkL);
    cudaGetSymbolAddress((void**)&edpkH, g_edpkH);
    cudaGetSymbolAddress((void**)&edpkL, g_edpkL);
    cudaGetSymbolAddress((void**)&wpkH, g_wpkH);
    cudaGetSymbolAddress((void**)&wpkL, g_wpkL);
    cudaGetSymbolAddress((void**)&cnt, g_cnt);
    cudaGetSymbolAddress((void**)&cur, g_cur);
    cudaGetSymbolAddress((void**)&off1, g_off1);
    cudaGetSymbolAddress((void**)&off2, g_off2);
    cudaGetSymbolAddress((void**)&off3, g_off3);
    cudaGetSymbolAddress((void**)&edg1, g_edg1);
    cudaGetSymbolAddress((void**)&edg2, g_edg2);
    cudaGetSymbolAddress((void**)&edg3, g_edg3);

    const int FY = cdiv(F_NN, 128);   // 196
    const int EY = cdiv(E_NN, 128);   // 391

    // ---- CSR build ----
    const int NCNT = 2 * F_NN + E_NN;
    fill_int_kernel<<<cdiv(NCNT, 256), 256>>>(cnt, NCNT);
    hist_kernel<<<cdiv(P_NN, 256), 256>>>(nn, 1, P_NN, cnt);
    hist_kernel<<<cdiv(M_NN, 256), 256>>>(cob, 1, M_NN, cnt + F_NN);
    hist_kernel<<<cdiv(M_NN, 256), 256>>>(cob, 0, M_NN, cnt + 2 * F_NN);
    scan3_kernel<<<3, 1024>>>(cnt, cur, off1, off2, off3);
    csr_scatter_kernel<<<cdiv(P_NN, 256), 256>>>(nn, 1, P_NN, cur, edg1);
    csr_scatter_kernel<<<cdiv(M_NN, 256), 256>>>(cob, 1, M_NN, cur + F_NN, edg2);
    csr_scatter_kernel<<<cdiv(M_NN, 256), 256>>>(cob, 0, M_NN, cur + 2 * F_NN, edg3);

    // ---- weight conversion (single kernel, [l][kpair][N]) ----
    WSpec wsp;
    {
        const float* Ws[12] = {aggr_W, ctr_W, f_Wq, f_Wk, f_Wv, f_We, f_Ws,
                               e_Wq, e_Wk, e_Wv, e_We, e_Ws};
        int Ns[12] = {128, 128, 384, 384, 384, 384, 128, 384, 384, 384, 384, 128};
        int Ls[12] = {1, 1, 3, 3, 3, 3, 3, 1, 1, 1, 1, 1};
        int o = 0;
        for (int i = 0; i < 12; i++) {
            wsp.W[i] = Ws[i];
            wsp.start[i] = o;
            wsp.N[i] = Ns[i];
            o += 64 * Ns[i] * Ls[i];
        }
        wsp.total = o;
    }
    conv_w_all_kernel<<<cdiv(wsp.total, 256), 256>>>(wsp, wpkH, wpkL);
    const int o_aggr = wsp.start[0], o_ctr = wsp.start[1];
    const int o_fq = wsp.start[2], o_fk = wsp.start[3], o_fv = wsp.start[4];
    const int o_fwe = wsp.start[5], o_fws = wsp.start[6];
    const int o_eq = wsp.start[7], o_ek = wsp.start[8], o_ev = wsp.start[9];
    const int o_ewe = wsp.start[10], o_ews = wsp.start[11];

    // ---- pack h_dE once (E rows): used by all layer ep GEMMs + final q/ws ----
    conv_act_kernel<<<cdiv(E_NN * 32, 256), 256>>>(h_dE, E_NN, edpkH, edpkL);

    // ---- init: h0 = aggr@aggr_W + aggr_b + h_dF@ctr_W + ctr_b ----
    aggr_conv_kernel<<<cdiv(F_NN, 8), 256>>>(off2, edg2, cob, h_dE, apkH, apkL);
    {
        GSegs s1 = {};
        s1.BH[0] = wpkH + o_aggr; s1.BL[0] = wpkL + o_aggr; s1.bias[0] = aggr_b;
        s1.C[0] = h0; s1.N[0] = 128; s1.acc[0] = 0; s1.start[0] = 0; s1.nseg = 1;
        gemm_multi<<<dim3(1, FY), 256, GEMM_SMEM>>>(apkH, apkL, F_NN, s1);
    }
    conv_act_kernel<<<cdiv(F_NN * 32, 256), 256>>>(h_dF, F_NN, apkH, apkL);
    {
        GSegs s2 = {};
        s2.BH[0] = wpkH + o_ctr; s2.BL[0] = wpkL + o_ctr; s2.bias[0] = ctr_b;
        s2.C[0] = h0; s2.N[0] = 128; s2.acc[0] = 1; s2.start[0] = 0;
        s2.eH[0] = apkH; s2.eL[0] = apkL;   // emit packed h0 for layer-1 GEMM
        s2.nseg = 1;
        gemm_multi<<<dim3(1, FY), 256, GEMM_SMEM>>>(apkH, apkL, F_NN, s2);
    }

    float* hcur = h0;
    float* hnext = h1;
    for (int l = 0; l < 3; l++) {
        const float* bq = f_bq + (size_t)l * 384;
        const float* bk = f_bk + (size_t)l * 384;
        const float* bv = f_bv + (size_t)l * 384;
        const float* bs = f_bs + (size_t)l * 128;
        const int lo384 = l * 64 * 384;
        const int lo128 = l * 64 * 128;

        // fused q,k,v,Ws over F rows
        GSegs sq = {};
        sq.BH[0] = wpkH + o_fq + lo384;  sq.BL[0] = wpkL + o_fq + lo384;
        sq.bias[0] = bq; sq.C[0] = q;   sq.N[0] = 384; sq.acc[0] = 0; sq.start[0] = 0;
        sq.BH[1] = wpkH + o_fk + lo384;  sq.BL[1] = wpkL + o_fk + lo384;
        sq.bias[1] = bk; sq.C[1] = k;   sq.N[1] = 384; sq.acc[1] = 0; sq.start[1] = 3;
        sq.BH[2] = wpkH + o_fv + lo384;  sq.BL[2] = wpkL + o_fv + lo384;
        sq.bias[2] = bv; sq.C[2] = v;   sq.N[2] = 384; sq.acc[2] = 0; sq.start[2] = 6;
        sq.BH[3] = wpkH + o_fws + lo128; sq.BL[3] = wpkL + o_fws + lo128;
        sq.bias[3] = bs; sq.C[3] = wsF; sq.N[3] = 128; sq.acc[3] = 0; sq.start[3] = 9;
        sq.nseg = 4;
        gemm_multi<<<dim3(10, FY), 256, GEMM_SMEM>>>(apkH, apkL, F_NN, sq);

        // epE = h_dE @ We (E unique rows; attention gathers epE[nn[:,2]])
        GSegs se = {};
        se.BH[0] = wpkH + o_fwe + lo384; se.BL[0] = wpkL + o_fwe + lo384;
        se.bias[0] = nullptr; se.C[0] = ep; se.N[0] = 384; se.acc[0] = 0; se.start[0] = 0;
        se.nseg = 1;
        gemm_multi<<<dim3(3, EY), 256, GEMM_SMEM>>>(edpkH, edpkL, E_NN, se);

        // fused attention + residual + Ws + next-layer packing
        attn_csr_kernel<<<cdiv(F_NN, 8), 256>>>(off1, edg1, nn, 0, 2, -1,
                                                q, k, v, ep, hcur, wsF,
                                                hnext, apkH, apkL, F_NN);

        float* tmp = hcur; hcur = hnext; hnext = tmp;
    }

    // ---- final cross attention: F -> E over cobdry edges ----
    {
        // q (E rows) + wsE from packed h_dE
        GSegs sq = {};
        sq.BH[0] = wpkH + o_eq;  sq.BL[0] = wpkL + o_eq;
        sq.bias[0] = e_bq; sq.C[0] = q;   sq.N[0] = 384; sq.acc[0] = 0; sq.start[0] = 0;
        sq.BH[1] = wpkH + o_ews; sq.BL[1] = wpkL + o_ews;
        sq.bias[1] = e_bs; sq.C[1] = wsE; sq.N[1] = 128; sq.acc[1] = 0; sq.start[1] = 3;
        sq.nseg = 2;
        gemm_multi<<<dim3(4, EY), 256, GEMM_SMEM>>>(edpkH, edpkL, E_NN, sq);

        // k + v + hWe over F rows (packed hcur from layer-3 attention)
        GSegs skv = {};
        skv.BH[0] = wpkH + o_ek;  skv.BL[0] = wpkL + o_ek;
        skv.bias[0] = e_bk; skv.C[0] = k;  skv.N[0] = 384; skv.acc[0] = 0; skv.start[0] = 0;
        skv.BH[1] = wpkH + o_ev;  skv.BL[1] = wpkL + o_ev;
        skv.bias[1] = e_bv; skv.C[1] = v;  skv.N[1] = 384; skv.acc[1] = 0; skv.start[1] = 3;
        skv.BH[2] = wpkH + o_ewe; skv.BL[2] = wpkL + o_ewe;
        skv.bias[2] = nullptr; skv.C[2] = ep; skv.N[2] = 384; skv.acc[2] = 0; skv.start[2] = 6;
        skv.nseg = 3;
        gemm_multi<<<dim3(9, FY), 256, GEMM_SMEM>>>(apkH, apkL, F_NN, skv);

        // final attention: dst = e_col (CSR3); src = ep row = cob[:,1]; ep sign = cob[:,2]
        attn_csr_kernel<<<cdiv(E_NN, 8), 256>>>(off3, edg3, cob, 1, 1, 2,
                                                q, k, v, ep, nullptr, wsE,
                                                out, nullptr, nullptr, E_NN);
    }
}